// round 10
// baseline (speedup 1.0000x reference)
#include <cuda_runtime.h>
#include <math.h>

// Reference reduces to: x0 = exp(-50*((X-.5)^2+(Y-.5)^2)); 100x { x = 0.25*Mask1*(N+S+E+W) }
// (down-sweep / coarse solve / up-sweep are dead code w.r.t. the returned value)
//
// Persistent kernel: 128 CTAs (1/SM, single wave), 10 super-steps x 10 smem-resident
// steps; halo exchange via ping-pong global buffers + epoch grid barrier.
// Single compute body (R8 structure). STS elision: stack rows 1,2 are stored only
// by edge lanes (their cross-thread readers) except on the last step of each
// super-step, where all rows are stored (write-back/reload read the full buffer).
// Intermediate write-backs store only the 10-wide ring neighbors actually read.

#define H 1024
#define NT 100
#define TSTEPS 10
#define NSS (NT / TSTEPS)               // 10 super-steps
#define TILE_W 128
#define TILE_H 64
#define HALO TSTEPS                     // 10
#define EXW (TILE_W + 2 * HALO)         // 148
#define EXH (TILE_H + 2 * HALO)         // 84
#define PITCH 148
#define GPR 37
#define NBANDS (EXH / 4)                // 21
#define NSTACKS (NBANDS * GPR)          // 777
#define NTHREADS 1024
#define ACT_WARPS ((NSTACKS + 31) / 32) // 25
#define GRID_X (H / TILE_W)             // 8
#define GRID_Y (H / TILE_H)             // 16
#define NCTA (GRID_X * GRID_Y)          // 128
#define SMEM_FLOATS (EXH * PITCH)       // 12432
#define SMEM_BYTES (2 * SMEM_FLOATS * 4)  // 99456 B -> 1 CTA/SM

typedef unsigned long long u64;

__device__ float g_buf0[H * H];
__device__ float g_buf1[H * H];
__device__ volatile unsigned g_arr[NCTA];   // zero-init; epochs, monotone across replays
__device__ volatile unsigned g_go;

__device__ __forceinline__ u64 addx2(u64 a, u64 b) {
    u64 r; asm("add.rn.f32x2 %0,%1,%2;" : "=l"(r) : "l"(a), "l"(b)); return r;
}
__device__ __forceinline__ u64 mulx2(u64 a, u64 b) {
    u64 r; asm("mul.rn.f32x2 %0,%1,%2;" : "=l"(r) : "l"(a), "l"(b)); return r;
}
__device__ __forceinline__ u64 pk(float lo, float hi) {
    u64 r; asm("mov.b64 %0,{%1,%2};" : "=l"(r) : "f"(lo), "f"(hi)); return r;
}
__device__ __forceinline__ void unpk(u64 a, float& lo, float& hi) {
    asm("mov.b64 {%0,%1},%2;" : "=f"(lo), "=f"(hi) : "l"(a));
}

// Epoch grid barrier. All 128 CTAs co-resident (1 CTA/SM, grid < SM count).
__device__ __forceinline__ void grid_barrier(int bid, unsigned ep) {
    __syncthreads();
    if (threadIdx.x == 0) {
        __threadfence();
        g_arr[bid] = ep;
    }
    if (bid == 0) {
        if (threadIdx.x < NCTA) {
            while (g_arr[threadIdx.x] < ep) __nanosleep(32);
        }
        __syncthreads();
        if (threadIdx.x == 0) { __threadfence(); g_go = ep; }
    }
    if (threadIdx.x == 0) {
        while (g_go < ep) __nanosleep(32);
        __threadfence();
    }
    __syncthreads();
}

__global__ void __launch_bounds__(NTHREADS, 1)
jacobi_persist(const float* __restrict__ X, const float* __restrict__ Y,
               const float* __restrict__ mask, float* __restrict__ out) {
    extern __shared__ float smem[];
    float* xs0 = smem;
    float* xs1 = smem + SMEM_FLOATS;

    const int bx = blockIdx.x, by = blockIdx.y;
    const int bid = by * GRID_X + bx;
    const int r0b = by * TILE_H - HALO;
    const int c0  = bx * TILE_W - HALO;
    const int tid = threadIdx.x;
    const int lane = tid & 31;
    const int wid = tid >> 5;

    const unsigned ep0 = g_arr[0];   // equal across CTAs at launch start

    // Initial fill: x0 = exp(-50*((X-.5)^2+(Y-.5)^2)), zero outside domain.
    for (int i = tid; i < SMEM_FLOATS; i += NTHREADS) {
        int r = i / PITCH;
        int c = i - r * PITCH;
        int gr = r0b + r;
        int gc = c0 + c;
        float v = 0.f;
        if ((unsigned)gr < (unsigned)H && (unsigned)gc < (unsigned)H) {
            int g = gr * H + gc;
            float dx = X[g] - 0.5f;
            float dy = Y[g] - 0.5f;
            v = expf(-50.0f * (dx * dx + dy * dy));
        }
        xs0[i] = v;
    }

    const bool act = tid < NSTACKS;
    int band = tid / GPR;
    int cg   = tid - band * GPR;
    if (!act) { band = NBANDS - 1; cg = GPR - 1; }   // clamp: valid addrs, no stores
    const int r0 = band * 4;
    const int o0 = r0 * PITCH + 4 * cg;
    const bool has_up = (band > 0);
    const bool has_dn = (band < NBANDS - 1);
    const bool edge_lane = (lane == 0) || (lane == 31);

    // Premultiplied mask into packed registers (bounds-checked, zero outside).
    u64 m01[4], m23[4];
    #pragma unroll
    for (int i = 0; i < 4; i++) {
        float a = 0.f, b = 0.f, c = 0.f, d = 0.f;
        int gr = r0b + r0 + i;
        if (act && (unsigned)gr < (unsigned)H) {
            const float* mrow = mask + gr * H;
            int gc = c0 + 4 * cg;
            if ((unsigned)gc       < (unsigned)H) a = 0.25f * mrow[gc];
            if ((unsigned)(gc + 1) < (unsigned)H) b = 0.25f * mrow[gc + 1];
            if ((unsigned)(gc + 2) < (unsigned)H) c = 0.25f * mrow[gc + 2];
            if ((unsigned)(gc + 3) < (unsigned)H) d = 0.25f * mrow[gc + 3];
        }
        m01[i] = pk(a, b);
        m23[i] = pk(c, d);
    }
    __syncthreads();

    // Center values into packed registers.
    u64 c01[4], c23[4];
    #pragma unroll
    for (int i = 0; i < 4; i++) {
        ulonglong2 v = *(const ulonglong2*)(xs0 + o0 + i * PITCH);
        c01[i] = v.x;
        c23[i] = v.y;
    }

    #pragma unroll 1
    for (int ss = 0; ss < NSS; ss++) {
        // ---- 10 smem-resident steps (ends with data in xs0). Single body. ----
        if (wid < ACT_WARPS) {
            float* cur = xs0;
            float* nxt = xs1;
            #pragma unroll
            for (int s = 1; s <= TSTEPS; s++) {
                bool rc[4];
                #pragma unroll
                for (int i = 0; i < 4; i++) {
                    int r = r0 + i;
                    rc[i] = act && (r >= s) && (r < EXH - s);
                }
                ulonglong2 uu = has_up ? *(const ulonglong2*)(cur + o0 - PITCH)
                                       : make_ulonglong2(0ull, 0ull);
                ulonglong2 dd = has_dn ? *(const ulonglong2*)(cur + o0 + 4 * PITCH)
                                       : make_ulonglong2(0ull, 0ull);

                u64 b01 = uu.x, b23 = uu.y;
                #pragma unroll
                for (int i = 0; i < 4; i++) {
                    float cx, cy, cz, cw;
                    unpk(c01[i], cx, cy);
                    unpk(c23[i], cz, cw);
                    float l  = __shfl_up_sync(0xffffffffu, cw, 1);
                    float rr = __shfl_down_sync(0xffffffffu, cx, 1);
                    int oi = o0 + i * PITCH;
                    if (lane == 0  && rc[i]) l  = cur[oi - 1];
                    if (lane == 31 && rc[i]) rr = cur[oi + 4];
                    u64 dn01, dn23;
                    if (i == 3) { dn01 = dd.x; dn23 = dd.y; }
                    else        { dn01 = c01[i + 1]; dn23 = c23[i + 1]; }
                    u64 mid = pk(cy, cz);
                    u64 h01 = addx2(pk(l, cx), mid);
                    u64 h23 = addx2(mid, pk(cw, rr));
                    u64 v01 = mulx2(addx2(addx2(b01, dn01), h01), m01[i]);
                    u64 v23 = mulx2(addx2(addx2(b23, dn23), h23), m23[i]);
                    b01 = c01[i];
                    b23 = c23[i];
                    if (rc[i]) {
                        c01[i] = v01;
                        c23[i] = v23;
                        // Rows 1,2 cross-thread readers: edge-lane fallbacks (their
                        // neighbor threads ARE edge lanes) and post-step-10 full
                        // consumers. i/s terms fold at compile time.
                        if (i == 0 || i == 3 || s == TSTEPS || edge_lane)
                            *(ulonglong2*)(nxt + oi) = make_ulonglong2(v01, v23);
                    }
                }
                float* t = cur; cur = nxt; nxt = t;
                __syncthreads();
            }
        } else {
            #pragma unroll
            for (int s = 1; s <= TSTEPS; s++) __syncthreads();
        }

        if (ss == NSS - 1) {
            // ---- final: write full interior (rows/cols [HALO,HALO+TILE)) to out ----
            #pragma unroll
            for (int k = 0; k < (TILE_H * TILE_W) / NTHREADS; k++) {   // 8 iterations
                int idx = tid + k * NTHREADS;
                int r = HALO + (idx >> 7);
                int c = HALO + (idx & 127);
                out[(r0b + r) * H + (c0 + c)] = xs0[r * PITCH + c];
            }
            break;
        }

        // ---- intermediate: write only the 10-wide ring neighbors read ----
        float* wb = (ss & 1) ? g_buf1 : g_buf0;
        // top/bottom bands: interior rows [0,10) and [54,64), all 128 cols
        for (int i = tid; i < 2 * HALO * TILE_W; i += NTHREADS) {     // 2560
            int r = i >> 7;            // 0..19
            int c = i & 127;
            if (r >= HALO) r += (TILE_H - 2 * HALO);   // -> 54..63
            int rr2 = HALO + r;
            int cc2 = HALO + c;
            wb[(r0b + rr2) * H + (c0 + cc2)] = xs0[rr2 * PITCH + cc2];
        }
        // side bands: interior rows [10,54), cols [0,10) and [118,128)
        for (int i = tid; i < (TILE_H - 2 * HALO) * 2 * HALO; i += NTHREADS) { // 880
            int r = i / (2 * HALO);
            int c = i - r * (2 * HALO);
            if (c >= HALO) c += (TILE_W - 2 * HALO);   // -> 118..127
            int rr2 = HALO + HALO + r;
            int cc2 = HALO + c;
            wb[(r0b + rr2) * H + (c0 + cc2)] = xs0[rr2 * PITCH + cc2];
        }

        grid_barrier(bid, ep0 + (unsigned)ss + 1u);

        // ---- refresh halo ring of xs0 from this super-step's buffer ----
        const float* rb = (ss & 1) ? g_buf1 : g_buf0;
        for (int i = tid; i < 2 * HALO * EXW; i += NTHREADS) {
            int r = i / EXW;
            int c = i - r * EXW;
            if (r >= HALO) r += TILE_H;
            int gr = r0b + r;
            int gc = c0 + c;
            float v = 0.f;
            if ((unsigned)gr < (unsigned)H && (unsigned)gc < (unsigned)H)
                v = rb[gr * H + gc];
            xs0[r * PITCH + c] = v;
        }
        for (int i = tid; i < TILE_H * 2 * HALO; i += NTHREADS) {
            int rr2 = i / (2 * HALO);
            int cc  = i - rr2 * (2 * HALO);
            int r = HALO + rr2;
            int c = (cc < HALO) ? cc : cc + TILE_W;
            int gr = r0b + r;
            int gc = c0 + c;
            float v = 0.f;
            if ((unsigned)gr < (unsigned)H && (unsigned)gc < (unsigned)H)
                v = rb[gr * H + gc];
            xs0[r * PITCH + c] = v;
        }
        __syncthreads();

        // ---- reload center registers from refreshed xs0 ----
        #pragma unroll
        for (int i = 0; i < 4; i++) {
            ulonglong2 v = *(const ulonglong2*)(xs0 + o0 + i * PITCH);
            c01[i] = v.x;
            c23[i] = v.y;
        }
        __syncthreads();
    }
}

extern "C" void kernel_launch(void* const* d_in, const int* in_sizes, int n_in,
                              void* d_out, int out_size) {
    (void)in_sizes; (void)n_in; (void)out_size;
    const float* X  = (const float*)d_in[0];
    const float* Y  = (const float*)d_in[1];
    const float* M1 = (const float*)d_in[2];   // Mask1: [1,1,1024,1024]
    float* out = (float*)d_out;

    cudaFuncSetAttribute(jacobi_persist, cudaFuncAttributeMaxDynamicSharedMemorySize,
                         SMEM_BYTES);

    dim3 grid(GRID_X, GRID_Y);   // (8, 16) = 128 CTAs, single wave on 148 SMs
    jacobi_persist<<<grid, NTHREADS, SMEM_BYTES>>>(X, Y, M1, out);
}

// round 11
// speedup vs baseline: 1.1100x; 1.1100x over previous
#include <cuda_runtime.h>
#include <math.h>

// Reference reduces to: x0 = exp(-50*((X-.5)^2+(Y-.5)^2)); 100x { x = 0.25*Mask1*(N+S+E+W) }
// (down-sweep / coarse solve / up-sweep are dead code w.r.t. the returned value)
//
// Persistent kernel: 128 CTAs (1/SM, single wave), 10 super-steps x 10 smem-resident
// steps; halo exchange via ping-pong global buffers + epoch grid barrier.
// R8 structure (full STS, full interior write-back). Change vs R8: the per-step CTA
// barrier is a named barrier (id 1, 800 threads) executed only by the 25 active
// warps; the 7 idle warps skip the step loop and rendezvous at barrier 0 after it.

#define H 1024
#define NT 100
#define TSTEPS 10
#define NSS (NT / TSTEPS)               // 10 super-steps
#define TILE_W 128
#define TILE_H 64
#define HALO TSTEPS                     // 10
#define EXW (TILE_W + 2 * HALO)         // 148
#define EXH (TILE_H + 2 * HALO)         // 84
#define PITCH 148
#define GPR 37
#define NBANDS (EXH / 4)                // 21
#define NSTACKS (NBANDS * GPR)          // 777
#define NTHREADS 1024
#define ACT_WARPS ((NSTACKS + 31) / 32) // 25
#define ACT_THREADS (ACT_WARPS * 32)    // 800
#define GRID_X (H / TILE_W)             // 8
#define GRID_Y (H / TILE_H)             // 16
#define NCTA (GRID_X * GRID_Y)          // 128
#define SMEM_FLOATS (EXH * PITCH)       // 12432
#define SMEM_BYTES (2 * SMEM_FLOATS * 4)  // 99456 B -> 1 CTA/SM

typedef unsigned long long u64;

__device__ float g_buf0[H * H];
__device__ float g_buf1[H * H];
__device__ volatile unsigned g_arr[NCTA];   // zero-init; epochs, monotone across replays
__device__ volatile unsigned g_go;

__device__ __forceinline__ u64 addx2(u64 a, u64 b) {
    u64 r; asm("add.rn.f32x2 %0,%1,%2;" : "=l"(r) : "l"(a), "l"(b)); return r;
}
__device__ __forceinline__ u64 mulx2(u64 a, u64 b) {
    u64 r; asm("mul.rn.f32x2 %0,%1,%2;" : "=l"(r) : "l"(a), "l"(b)); return r;
}
__device__ __forceinline__ u64 pk(float lo, float hi) {
    u64 r; asm("mov.b64 %0,{%1,%2};" : "=l"(r) : "f"(lo), "f"(hi)); return r;
}
__device__ __forceinline__ void unpk(u64 a, float& lo, float& hi) {
    asm("mov.b64 {%0,%1},%2;" : "=f"(lo), "=f"(hi) : "l"(a));
}

// Named barrier for the 25 active warps only (barrier id 1).
__device__ __forceinline__ void act_barrier() {
    asm volatile("bar.sync 1, %0;" :: "n"(ACT_THREADS) : "memory");
}

// Epoch grid barrier. All 128 CTAs co-resident (1 CTA/SM, grid < SM count).
__device__ __forceinline__ void grid_barrier(int bid, unsigned ep) {
    __syncthreads();
    if (threadIdx.x == 0) {
        __threadfence();
        g_arr[bid] = ep;
    }
    if (bid == 0) {
        if (threadIdx.x < NCTA) {
            while (g_arr[threadIdx.x] < ep) __nanosleep(32);
        }
        __syncthreads();
        if (threadIdx.x == 0) { __threadfence(); g_go = ep; }
    }
    if (threadIdx.x == 0) {
        while (g_go < ep) __nanosleep(32);
        __threadfence();
    }
    __syncthreads();
}

__global__ void __launch_bounds__(NTHREADS, 1)
jacobi_persist(const float* __restrict__ X, const float* __restrict__ Y,
               const float* __restrict__ mask, float* __restrict__ out) {
    extern __shared__ float smem[];
    float* xs0 = smem;
    float* xs1 = smem + SMEM_FLOATS;

    const int bx = blockIdx.x, by = blockIdx.y;
    const int bid = by * GRID_X + bx;
    const int r0b = by * TILE_H - HALO;
    const int c0  = bx * TILE_W - HALO;
    const int tid = threadIdx.x;
    const int lane = tid & 31;
    const int wid = tid >> 5;

    const unsigned ep0 = g_arr[0];   // equal across CTAs at launch start

    // Initial fill: x0 = exp(-50*((X-.5)^2+(Y-.5)^2)), zero outside domain.
    for (int i = tid; i < SMEM_FLOATS; i += NTHREADS) {
        int r = i / PITCH;
        int c = i - r * PITCH;
        int gr = r0b + r;
        int gc = c0 + c;
        float v = 0.f;
        if ((unsigned)gr < (unsigned)H && (unsigned)gc < (unsigned)H) {
            int g = gr * H + gc;
            float dx = X[g] - 0.5f;
            float dy = Y[g] - 0.5f;
            v = expf(-50.0f * (dx * dx + dy * dy));
        }
        xs0[i] = v;
    }

    const bool act = tid < NSTACKS;
    int band = tid / GPR;
    int cg   = tid - band * GPR;
    if (!act) { band = NBANDS - 1; cg = GPR - 1; }   // clamp: valid addrs, no stores
    const int r0 = band * 4;
    const int o0 = r0 * PITCH + 4 * cg;
    const bool has_up = (band > 0);
    const bool has_dn = (band < NBANDS - 1);

    // Premultiplied mask into packed registers (bounds-checked, zero outside).
    u64 m01[4], m23[4];
    #pragma unroll
    for (int i = 0; i < 4; i++) {
        float a = 0.f, b = 0.f, c = 0.f, d = 0.f;
        int gr = r0b + r0 + i;
        if (act && (unsigned)gr < (unsigned)H) {
            const float* mrow = mask + gr * H;
            int gc = c0 + 4 * cg;
            if ((unsigned)gc       < (unsigned)H) a = 0.25f * mrow[gc];
            if ((unsigned)(gc + 1) < (unsigned)H) b = 0.25f * mrow[gc + 1];
            if ((unsigned)(gc + 2) < (unsigned)H) c = 0.25f * mrow[gc + 2];
            if ((unsigned)(gc + 3) < (unsigned)H) d = 0.25f * mrow[gc + 3];
        }
        m01[i] = pk(a, b);
        m23[i] = pk(c, d);
    }
    __syncthreads();

    // Center values into packed registers.
    u64 c01[4], c23[4];
    #pragma unroll
    for (int i = 0; i < 4; i++) {
        ulonglong2 v = *(const ulonglong2*)(xs0 + o0 + i * PITCH);
        c01[i] = v.x;
        c23[i] = v.y;
    }

    #pragma unroll 1
    for (int ss = 0; ss < NSS; ss++) {
        // ---- 10 smem-resident steps (ends with data in xs0). Active warps only;
        //      idle warps skip and wait at the barrier-0 rendezvous below. ----
        if (wid < ACT_WARPS) {
            float* cur = xs0;
            float* nxt = xs1;
            #pragma unroll
            for (int s = 1; s <= TSTEPS; s++) {
                bool rc[4];
                #pragma unroll
                for (int i = 0; i < 4; i++) {
                    int r = r0 + i;
                    rc[i] = act && (r >= s) && (r < EXH - s);
                }
                ulonglong2 uu = has_up ? *(const ulonglong2*)(cur + o0 - PITCH)
                                       : make_ulonglong2(0ull, 0ull);
                ulonglong2 dd = has_dn ? *(const ulonglong2*)(cur + o0 + 4 * PITCH)
                                       : make_ulonglong2(0ull, 0ull);

                u64 b01 = uu.x, b23 = uu.y;
                #pragma unroll
                for (int i = 0; i < 4; i++) {
                    float cx, cy, cz, cw;
                    unpk(c01[i], cx, cy);
                    unpk(c23[i], cz, cw);
                    float l  = __shfl_up_sync(0xffffffffu, cw, 1);
                    float rr = __shfl_down_sync(0xffffffffu, cx, 1);
                    int oi = o0 + i * PITCH;
                    if (lane == 0  && rc[i]) l  = cur[oi - 1];
                    if (lane == 31 && rc[i]) rr = cur[oi + 4];
                    u64 dn01, dn23;
                    if (i == 3) { dn01 = dd.x; dn23 = dd.y; }
                    else        { dn01 = c01[i + 1]; dn23 = c23[i + 1]; }
                    u64 mid = pk(cy, cz);
                    u64 h01 = addx2(pk(l, cx), mid);
                    u64 h23 = addx2(mid, pk(cw, rr));
                    u64 v01 = mulx2(addx2(addx2(b01, dn01), h01), m01[i]);
                    u64 v23 = mulx2(addx2(addx2(b23, dn23), h23), m23[i]);
                    b01 = c01[i];
                    b23 = c23[i];
                    if (rc[i]) {
                        c01[i] = v01;
                        c23[i] = v23;
                        *(ulonglong2*)(nxt + oi) = make_ulonglong2(v01, v23);
                    }
                }
                float* t = cur; cur = nxt; nxt = t;
                act_barrier();
            }
        }
        // Rendezvous of all 32 warps (idle warps arrive early and wait).
        __syncthreads();

        // ---- write interior (rows/cols [HALO, HALO+TILE)) from xs0 ----
        float* wb = (ss == NSS - 1) ? out : ((ss & 1) ? g_buf1 : g_buf0);
        #pragma unroll
        for (int k = 0; k < (TILE_H * TILE_W) / NTHREADS; k++) {   // 8 iterations
            int idx = tid + k * NTHREADS;
            int r = HALO + (idx >> 7);
            int c = HALO + (idx & 127);
            wb[(r0b + r) * H + (c0 + c)] = xs0[r * PITCH + c];
        }
        if (ss == NSS - 1) break;

        grid_barrier(bid, ep0 + (unsigned)ss + 1u);

        // ---- refresh halo ring of xs0 from this super-step's buffer ----
        const float* rb = (ss & 1) ? g_buf1 : g_buf0;
        for (int i = tid; i < 2 * HALO * EXW; i += NTHREADS) {
            int r = i / EXW;
            int c = i - r * EXW;
            if (r >= HALO) r += TILE_H;
            int gr = r0b + r;
            int gc = c0 + c;
            float v = 0.f;
            if ((unsigned)gr < (unsigned)H && (unsigned)gc < (unsigned)H)
                v = rb[gr * H + gc];
            xs0[r * PITCH + c] = v;
        }
        for (int i = tid; i < TILE_H * 2 * HALO; i += NTHREADS) {
            int rr2 = i / (2 * HALO);
            int cc  = i - rr2 * (2 * HALO);
            int r = HALO + rr2;
            int c = (cc < HALO) ? cc : cc + TILE_W;
            int gr = r0b + r;
            int gc = c0 + c;
            float v = 0.f;
            if ((unsigned)gr < (unsigned)H && (unsigned)gc < (unsigned)H)
                v = rb[gr * H + gc];
            xs0[r * PITCH + c] = v;
        }
        __syncthreads();

        // ---- reload center registers from refreshed xs0 ----
        #pragma unroll
        for (int i = 0; i < 4; i++) {
            ulonglong2 v = *(const ulonglong2*)(xs0 + o0 + i * PITCH);
            c01[i] = v.x;
            c23[i] = v.y;
        }
        __syncthreads();
    }
}

extern "C" void kernel_launch(void* const* d_in, const int* in_sizes, int n_in,
                              void* d_out, int out_size) {
    (void)in_sizes; (void)n_in; (void)out_size;
    const float* X  = (const float*)d_in[0];
    const float* Y  = (const float*)d_in[1];
    const float* M1 = (const float*)d_in[2];   // Mask1: [1,1,1024,1024]
    float* out = (float*)d_out;

    cudaFuncSetAttribute(jacobi_persist, cudaFuncAttributeMaxDynamicSharedMemorySize,
                         SMEM_BYTES);

    dim3 grid(GRID_X, GRID_Y);   // (8, 16) = 128 CTAs, single wave on 148 SMs
    jacobi_persist<<<grid, NTHREADS, SMEM_BYTES>>>(X, Y, M1, out);
}